// round 4
// baseline (speedup 1.0000x reference)
#include <cuda_runtime.h>
#include <math.h>

#define MAXN 10000
#define MAXE 320000

typedef unsigned long long u64;

// Scratch (__device__ globals per allocation-free rule)
__device__ float g_y[MAXN * 256];     // [node]: y0[64] | y1 m-major (64+m*64+v), scale 1/8 folded
__device__ float g_agg[MAXN * 512];   // reference concat layout, LIN2S (1/64) folded
__device__ float g_h[MAXE * 8];       // edge MLP hidden, INV_SQRT8 (2nd layer scale) folded
__device__ int   g_deg[MAXN];
__device__ int   g_row[MAXN + 1];
__device__ int   g_cursor[MAXN];
__device__ int2  g_epair[MAXE];       // (src, eid) per CSR slot

#define INV_SQRT8 0.35355339059327373f
#define INV_SQRT3 0.5773502691896258f
#define LOG2F_C   0.6931471805599453f
#define LIN2S     0.015625f   // 1/(sqrt(32)*sqrt(128))
#define SCN       0.0625f     // 1/sqrt(64*4)

// ---- Blackwell packed f32x2 helpers --------------------------------------
__device__ __forceinline__ u64 pk2(float lo, float hi) {
    u64 r; asm("mov.b64 %0,{%1,%2};" : "=l"(r) : "f"(lo), "f"(hi)); return r;
}
__device__ __forceinline__ u64 dup2(float x) { return pk2(x, x); }
__device__ __forceinline__ float2 unpk2(u64 v) {
    float2 f; asm("mov.b64 {%0,%1},%2;" : "=f"(f.x), "=f"(f.y) : "l"(v)); return f;
}
__device__ __forceinline__ u64 fma2(u64 a, u64 b, u64 c) {
    u64 d; asm("fma.rn.f32x2 %0,%1,%2,%3;" : "=l"(d) : "l"(a), "l"(b), "l"(c)); return d;
}
__device__ __forceinline__ u64 mul2(u64 a, u64 b) {
    u64 d; asm("mul.rn.f32x2 %0,%1,%2;" : "=l"(d) : "l"(a), "l"(b)); return d;
}

// ---------------------------------------------------------------------------
__global__ void zero_deg_kernel(int n) {
    int i = blockIdx.x * blockDim.x + threadIdx.x;
    if (i < n) g_deg[i] = 0;
}

__global__ void count_kernel(const int* __restrict__ eidx, int E) {
    int e = blockIdx.x * blockDim.x + threadIdx.x;
    if (e < E) atomicAdd(&g_deg[eidx[e]], 1);
}

// Single-block exclusive scan over g_deg -> g_row, g_cursor; g_row[n]=E.
__global__ void scan_kernel(int n) {
    __shared__ int part[1024];
    int tid = threadIdx.x;
    int IT = (n + 1023) >> 10;
    int base = tid * IT;
    int s = 0;
    for (int i = 0; i < IT; ++i) {
        int idx = base + i;
        if (idx < n) s += g_deg[idx];
    }
    part[tid] = s;
    __syncthreads();
    for (int off = 1; off < 1024; off <<= 1) {
        int v = (tid >= off) ? part[tid - off] : 0;
        __syncthreads();
        part[tid] += v;
        __syncthreads();
    }
    int run = part[tid] - s;
    for (int i = 0; i < IT; ++i) {
        int idx = base + i;
        if (idx < n) {
            g_row[idx] = run;
            g_cursor[idx] = run;
            run += g_deg[idx];
        }
    }
    if (tid == 1023) g_row[n] = part[1023];
}

// Scatter edge slot with (src, eid) payload so agg has a single-load chain.
__global__ void scatter_kernel(const int* __restrict__ eidx, int E) {
    int e = blockIdx.x * blockDim.x + threadIdx.x;
    if (e < E) {
        int dst = eidx[e];
        int src = eidx[E + e];
        int pos = atomicAdd(&g_cursor[dst], 1);
        g_epair[pos] = make_int2(src, e);
    }
}

// ---------------------------------------------------------------------------
// Edge MLP layer 1: h = (softplus(emb @ Wfc1 / sqrt(8)) - log2) * (1/sqrt(8))
__global__ void h_kernel(const float* __restrict__ eemb,
                         const float* __restrict__ Wfc1, int E) {
    __shared__ float sW1[64];
    int tid = threadIdx.x;
    if (tid < 64) sW1[tid] = Wfc1[tid];
    __syncthreads();
    int e = blockIdx.x * blockDim.x + tid;
    if (e >= E) return;
    float4 e0 = *(const float4*)(eemb + (size_t)e * 8);
    float4 e1 = *(const float4*)(eemb + (size_t)e * 8 + 4);
    float emb[8] = {e0.x, e0.y, e0.z, e0.w, e1.x, e1.y, e1.z, e1.w};
    float h[8];
    #pragma unroll
    for (int j = 0; j < 8; ++j) {
        float z = 0.f;
        #pragma unroll
        for (int k = 0; k < 8; ++k) z = fmaf(emb[k], sW1[k * 8 + j], z);
        z *= INV_SQRT8;
        float sp = (z > 20.f) ? z : log1pf(__expf(z));
        h[j] = (sp - LOG2F_C) * INV_SQRT8;
    }
    float* o = g_h + (size_t)e * 8;
    *(float4*)o       = make_float4(h[0], h[1], h[2], h[3]);
    *(float4*)(o + 4) = make_float4(h[4], h[5], h[6], h[7]);
}

// ---------------------------------------------------------------------------
// Node pre GEMMs, K=64 (both modes in one launch).
__global__ void pre_gemm_kernel(const float* __restrict__ nf,
                                const float* __restrict__ Wl10,
                                const float* __restrict__ Wl11,
                                int n, int nb0) {
    __shared__ __align__(16) float sIn[32 * 64];
    __shared__ __align__(16) float sW[64 * 64];
    int tid = threadIdx.x;
    int v = tid & 63, rgrp = tid >> 6;
    int mode = (blockIdx.x >= nb0) ? 1 : 0;
    int blk = mode ? (blockIdx.x - nb0) : blockIdx.x;
    int rows = mode ? 3 * n : n;
    int rbase = blk * 32;
    const float* W = mode ? Wl11 : Wl10;

    for (int i = tid; i < 4096; i += 256) sW[i] = W[i];
    for (int i = tid; i < 2048; i += 256) {
        int row = i >> 6, k = i & 63;
        int rg = rbase + row;
        float val = 0.f;
        if (rg < rows) {
            if (mode == 0) val = nf[(size_t)rg * 256 + k];
            else {
                int node = rg / 3, m = rg % 3;
                val = nf[(size_t)node * 256 + 64 + k * 3 + m];
            }
        }
        sIn[i] = val;
    }
    __syncthreads();

    float acc[8] = {0.f, 0.f, 0.f, 0.f, 0.f, 0.f, 0.f, 0.f};
    for (int kk = 0; kk < 64; kk += 4) {
        float w0 = sW[(kk + 0) * 64 + v];
        float w1 = sW[(kk + 1) * 64 + v];
        float w2 = sW[(kk + 2) * 64 + v];
        float w3 = sW[(kk + 3) * 64 + v];
        #pragma unroll
        for (int r = 0; r < 8; ++r) {
            const float4 in4 = *(const float4*)(sIn + (rgrp * 8 + r) * 64 + kk);
            acc[r] = fmaf(in4.x, w0, fmaf(in4.y, w1, fmaf(in4.z, w2, fmaf(in4.w, w3, acc[r]))));
        }
    }
    #pragma unroll
    for (int r = 0; r < 8; ++r) {
        int rg = rbase + rgrp * 8 + r;
        if (rg >= rows) continue;
        float val = acc[r] * 0.125f;
        if (mode == 0) g_y[(size_t)rg * 256 + v] = val;
        else {
            int node = rg / 3, m = rg % 3;
            g_y[(size_t)node * 256 + 64 + m * 64 + v] = val;
        }
    }
}

// ---------------------------------------------------------------------------
// Aggregation: block per node, 4 groups x 64 threads, register accumulators,
// packed-f32x2 weight reconstruction, (src,eid) prefetch. No atomics.
__global__ void __launch_bounds__(256) agg_kernel(const float* __restrict__ eattr,
                           const float* __restrict__ Wfc2,
                           int E, int n) {
    __shared__ float spart[4 * 512];
    int tid = threadIdx.x;
    int u = tid & 63, grp = tid >> 6;

    // Packed weight columns: (u, 64+u) and (128+u, 192+u*INV_SQRT3-folded)
    u64 wAB[8], wCD[8];
    #pragma unroll
    for (int j = 0; j < 8; ++j) {
        const float* r = Wfc2 + j * 256;
        wAB[j] = pk2(__ldg(r + u), __ldg(r + 64 + u));
        wCD[j] = pk2(__ldg(r + 128 + u), __ldg(r + 192 + u) * INV_SQRT3);
    }

    int node = blockIdx.x;
    int rs = g_row[node], re = g_row[node + 1];

    float a0 = 0.f, a1 = 0.f, a4 = 0.f, a7 = 0.f;
    u64 acc23 = 0ULL, acc56 = 0ULL;  // bit pattern of (0.f,0.f)

    int i = rs + grp;
    int2 pr = (i < re) ? __ldg(g_epair + i) : make_int2(0, 0);

    for (; i < re; i += 4) {
        int2 cur = pr;
        int inx = i + 4;
        if (inx < re) pr = __ldg(g_epair + inx);

        int src = cur.x, eid = cur.y;
        float4 sh = __ldg((const float4*)(eattr + (size_t)eid * 4));
        float4 h0 = __ldg((const float4*)(g_h + (size_t)eid * 8));
        float4 h1 = __ldg((const float4*)(g_h + (size_t)eid * 8 + 4));

        const float* ysrc = g_y + (size_t)src * 256;
        float xs0 = __ldg(ysrc + u);
        float x1x = __ldg(ysrc + 64 + u);
        float x1y = __ldg(ysrc + 128 + u);
        float x1z = __ldg(ysrc + 192 + u);

        u64 hd0 = dup2(h0.x), hd1 = dup2(h0.y), hd2 = dup2(h0.z), hd3 = dup2(h0.w);
        u64 hd4 = dup2(h1.x), hd5 = dup2(h1.y), hd6 = dup2(h1.z), hd7 = dup2(h1.w);

        u64 w12 = mul2(hd0, wAB[0]);
        w12 = fma2(hd1, wAB[1], w12);
        w12 = fma2(hd2, wAB[2], w12);
        w12 = fma2(hd3, wAB[3], w12);
        w12 = fma2(hd4, wAB[4], w12);
        w12 = fma2(hd5, wAB[5], w12);
        w12 = fma2(hd6, wAB[6], w12);
        w12 = fma2(hd7, wAB[7], w12);

        u64 w34 = mul2(hd0, wCD[0]);
        w34 = fma2(hd1, wCD[1], w34);
        w34 = fma2(hd2, wCD[2], w34);
        w34 = fma2(hd3, wCD[3], w34);
        w34 = fma2(hd4, wCD[4], w34);
        w34 = fma2(hd5, wCD[5], w34);
        w34 = fma2(hd6, wCD[6], w34);
        w34 = fma2(hd7, wCD[7], w34);

        float2 wf12 = unpk2(w12);
        float2 wf34 = unpk2(w34);
        float w1 = wf12.x, w2 = wf12.y, w3 = wf34.x, w4 = wf34.y;  // w4 has 1/sqrt(3) folded

        float dotv = fmaf(x1x, sh.y, fmaf(x1y, sh.z, x1z * sh.w));
        a0 = fmaf(w1 * xs0, sh.x, a0);
        a1 = fmaf(w4, dotv, a1);

        float a2c = w2 * xs0;
        float a3c = w3 * sh.x;
        acc23 = fma2(dup2(a2c), pk2(sh.y, sh.z), acc23);
        a4 = fmaf(a2c, sh.w, a4);
        acc56 = fma2(dup2(a3c), pk2(x1x, x1y), acc56);
        a7 = fmaf(a3c, x1z, a7);
    }

    float2 f23 = unpk2(acc23);
    float2 f56 = unpk2(acc56);

    float* sp = spart + grp * 512;
    sp[u] = a0;
    sp[64 + u] = a1;
    sp[128 + 3 * u + 0] = f23.x;
    sp[128 + 3 * u + 1] = f23.y;
    sp[128 + 3 * u + 2] = a4;
    sp[320 + 3 * u + 0] = f56.x;
    sp[320 + 3 * u + 1] = f56.y;
    sp[320 + 3 * u + 2] = a7;
    __syncthreads();

    float* arow = g_agg + (size_t)node * 512;
    for (int idx = tid; idx < 512; idx += 256)
        arow[idx] = (spart[idx] + spart[512 + idx] + spart[1024 + idx] + spart[1536 + idx]) * LIN2S;
}

// ---------------------------------------------------------------------------
// Node post GEMM, K=384 in 4 chunks of 96, packed-f32x2 row-pair math.
// Blocks [0,nb0) = o0 (n rows); [nb0,...) = o1 (3n rows).
__global__ void post_gemm_kernel(const float* __restrict__ nf,
                                 const float* __restrict__ attrs,
                                 const float* __restrict__ Wl20,
                                 const float* __restrict__ Wl21,
                                 const float* __restrict__ Wsc0,
                                 const float* __restrict__ Wsc1,
                                 float* __restrict__ out,
                                 int n, int nb0) {
    __shared__ __align__(16) float sW[96 * 64];       // 24 KB, k-major
    __shared__ __align__(16) float sInP[16 * 96 * 2]; // 12 KB: [rp][k][half]
    int tid = threadIdx.x;
    int v = tid & 63, rgrp = tid >> 6;
    int mode = (blockIdx.x >= nb0) ? 1 : 0;
    int blk = mode ? (blockIdx.x - nb0) : blockIdx.x;
    int rows = mode ? 3 * n : n;
    int rbase = blk * 32;
    const float* Wlin = mode ? Wl21 : Wl20;
    const float* Wsc  = mode ? Wsc1 : Wsc0;

    u64 accP[4] = {0ULL, 0ULL, 0ULL, 0ULL};  // row pairs (2r,2r+1) for r-pairs rgrp*4..+3

    for (int c = 0; c < 4; ++c) {
        // Weight chunk: sW[kk*64+v] = W[k= c*96+kk][v]
        for (int i = tid; i < 6144; i += 256) {
            int kk = i >> 6, vv = i & 63;
            int k = c * 96 + kk;
            float w;
            if (k < 128) w = Wlin[k * 64 + vv];
            else {
                int t2 = k - 128, a = t2 >> 6, uu = t2 & 63;
                w = Wsc[uu * 256 + a * 64 + vv];
            }
            sW[i] = w;
        }
        // Input chunk, row-pair interleaved: sInP[(row>>1)*192 + kk*2 + (row&1)]
        for (int i = tid; i < 3072; i += 256) {
            int row = i / 96, kk = i % 96;
            int rg = rbase + row;
            int k = c * 96 + kk;
            float val = 0.f;
            if (rg < rows) {
                if (mode == 0) {
                    if (k < 128) val = g_agg[(size_t)rg * 512 + k];
                    else {
                        int t2 = k - 128, a = t2 >> 6, uu = t2 & 63;
                        val = attrs[(size_t)rg * 4 + a] * nf[(size_t)rg * 256 + uu] * SCN;
                    }
                } else {
                    int node = rg / 3, m = rg % 3;
                    if (k < 128) val = g_agg[(size_t)node * 512 + 128 + k * 3 + m];
                    else {
                        int t2 = k - 128, a = t2 >> 6, uu = t2 & 63;
                        val = attrs[(size_t)node * 4 + a] * nf[(size_t)node * 256 + 64 + uu * 3 + m] * SCN;
                    }
                }
            }
            sInP[(row >> 1) * 192 + kk * 2 + (row & 1)] = val;
        }
        __syncthreads();

        #pragma unroll 4
        for (int kk = 0; kk < 96; kk += 4) {
            u64 wd0 = dup2(sW[(kk + 0) * 64 + v]);
            u64 wd1 = dup2(sW[(kk + 1) * 64 + v]);
            u64 wd2 = dup2(sW[(kk + 2) * 64 + v]);
            u64 wd3 = dup2(sW[(kk + 3) * 64 + v]);
            #pragma unroll
            for (int rl = 0; rl < 4; ++rl) {
                const u64* bp = (const u64*)(sInP + (rgrp * 4 + rl) * 192 + kk * 2);
                u64 a = accP[rl];
                a = fma2(bp[0], wd0, a);
                a = fma2(bp[1], wd1, a);
                a = fma2(bp[2], wd2, a);
                a = fma2(bp[3], wd3, a);
                accP[rl] = a;
            }
        }
        __syncthreads();
    }

    #pragma unroll
    for (int rl = 0; rl < 4; ++rl) {
        float2 pr = unpk2(accP[rl]);
        int r0 = rbase + (rgrp * 4 + rl) * 2;
        #pragma unroll
        for (int half = 0; half < 2; ++half) {
            int rg = r0 + half;
            if (rg >= rows) continue;
            float val = half ? pr.y : pr.x;
            if (mode == 0) out[(size_t)rg * 256 + v] = val;
            else {
                int node = rg / 3, m = rg % 3;
                out[(size_t)node * 256 + 64 + v * 3 + m] = val;
            }
        }
    }
}

// ---------------------------------------------------------------------------
extern "C" void kernel_launch(void* const* d_in, const int* in_sizes, int n_in,
                              void* d_out, int out_size) {
    const float* nf    = (const float*)d_in[0];
    const float* attrs = (const float*)d_in[1];
    const float* ea    = (const float*)d_in[2];
    const float* ee    = (const float*)d_in[3];
    const int*   ei    = (const int*)d_in[4];
    const float* Wl10  = (const float*)d_in[5];
    const float* Wl11  = (const float*)d_in[6];
    const float* Wfc1  = (const float*)d_in[7];
    const float* Wfc2  = (const float*)d_in[8];
    const float* Wl20  = (const float*)d_in[9];
    const float* Wl21  = (const float*)d_in[10];
    const float* Wsc0  = (const float*)d_in[11];
    const float* Wsc1  = (const float*)d_in[12];
    float* out = (float*)d_out;

    int n = in_sizes[0] / 256;
    int E = in_sizes[2] / 4;

    // CSR build (payload = (src, eid))
    zero_deg_kernel<<<(n + 255) / 256, 256>>>(n);
    count_kernel<<<(E + 255) / 256, 256>>>(ei, E);
    scan_kernel<<<1, 1024>>>(n);
    scatter_kernel<<<(E + 255) / 256, 256>>>(ei, E);

    // Edge MLP hidden layer
    h_kernel<<<(E + 255) / 256, 256>>>(ee, Wfc1, E);

    // Node pre (y0, y1) fused
    int pre_nb0 = (n + 31) / 32, pre_nb1 = (3 * n + 31) / 32;
    pre_gemm_kernel<<<pre_nb0 + pre_nb1, 256>>>(nf, Wl10, Wl11, n, pre_nb0);

    // Aggregation
    agg_kernel<<<n, 256>>>(ea, Wfc2, E, n);

    // Node post (o0, o1) fused
    int post_nb0 = (n + 31) / 32, post_nb1 = (3 * n + 31) / 32;
    post_gemm_kernel<<<post_nb0 + post_nb1, 256>>>(nf, attrs, Wl20, Wl21, Wsc0, Wsc1, out, n, post_nb0);
}